// round 5
// baseline (speedup 1.0000x reference)
#include <cuda_runtime.h>
#include <cuda_bf16.h>
#include <cstdint>

#define NVOX 40000
#define CCH  128
#define K27  27
#define BMT  128
#define GRIDM ((NVOX + BMT - 1) / BMT)   // 313

#define KCH    64                  // K per stage chunk (bf16 elems)
#define ASTRB  144                 // padded row stride bytes (64 bf16 = 128B + 16 pad)
#define TILE_B (128 * ASTRB)       // 18432 B
#define STAGE  (4 * TILE_B)        // Ah, Al, Bh, Bl = 73728 B
#define NSTG   3
#define SMEM_BYTES (NSTG * STAGE)  // 221184 B

// ---------------- persistent device scratch (zero-init) ---------------------
__device__ __nv_bfloat16 g_fh[(NVOX + 1) * CCH];    // feats split hi (pad row 0)
__device__ __nv_bfloat16 g_fl[(NVOX + 1) * CCH];
__device__ __nv_bfloat16 g_h1h[(NVOX + 1) * CCH];   // layer-1 out hi (pad row 0)
__device__ __nv_bfloat16 g_h1l[(NVOX + 1) * CCH];
__device__ __nv_bfloat16 g_w1h[K27 * CCH * CCH];    // W1^T [k][cout][cin]
__device__ __nv_bfloat16 g_w1l[K27 * CCH * CCH];
__device__ __nv_bfloat16 g_wch[64 * CCH * CCH];     // Wc [c][t][cout][cin]
__device__ __nv_bfloat16 g_wcl[64 * CCH * CCH];

// ---------------- helpers ----------------------------------------------------
__device__ __forceinline__ uint32_t smem_u32(const void* p) {
    uint32_t a;
    asm("{ .reg .u64 t; cvta.to.shared.u64 t, %1; cvt.u32.u64 %0, t; }" : "=r"(a) : "l"(p));
    return a;
}
__device__ __forceinline__ void bf16_split(float x, __nv_bfloat16& h, __nv_bfloat16& l) {
    h = __float2bfloat16_rn(x);
    l = __float2bfloat16_rn(x - __bfloat162float(h));
}
__device__ __forceinline__ uint32_t pack2(__nv_bfloat16 a, __nv_bfloat16 b) {
    uint16_t ua = *(uint16_t*)&a, ub = *(uint16_t*)&b;
    return (uint32_t)ua | ((uint32_t)ub << 16);
}
#define CP16(dst, src) asm volatile("cp.async.cg.shared.global [%0], [%1], 16;" :: "r"(dst), "l"(src) : "memory")
#define CP_COMMIT()    asm volatile("cp.async.commit_group;" ::: "memory")
#define CP_WAIT1()     asm volatile("cp.async.wait_group 1;" ::: "memory")
#define CP_WAIT0()     asm volatile("cp.async.wait_group 0;" ::: "memory")

__device__ __forceinline__ void ldsm4(uint32_t* r, uint32_t addr) {
    asm volatile("ldmatrix.sync.aligned.m8n8.x4.shared.b16 {%0,%1,%2,%3}, [%4];"
        : "=r"(r[0]), "=r"(r[1]), "=r"(r[2]), "=r"(r[3]) : "r"(addr));
}
__device__ __forceinline__ void mma_bf16(float* c, const uint32_t* a, const uint32_t* b) {
    asm volatile("mma.sync.aligned.m16n8k16.row.col.f32.bf16.bf16.f32 "
        "{%0,%1,%2,%3}, {%4,%5,%6,%7}, {%8,%9}, {%0,%1,%2,%3};"
        : "+f"(c[0]), "+f"(c[1]), "+f"(c[2]), "+f"(c[3])
        : "r"(a[0]), "r"(a[1]), "r"(a[2]), "r"(a[3]), "r"(b[0]), "r"(b[1]));
}

// ---------------- prep kernels ------------------------------------------------
__global__ void prep_feats(const float* __restrict__ feats) {
    int e = blockIdx.x * 256 + threadIdx.x;
    if (e >= NVOX * CCH) return;
    __nv_bfloat16 h, l; bf16_split(feats[e], h, l);
    g_fh[e] = h; g_fl[e] = l;
}
__global__ void prep_w1(const float* __restrict__ W1) {
    int e = blockIdx.x * 256 + threadIdx.x;
    if (e >= K27 * CCH * CCH) return;
    int j = e & 127, i = (e >> 7) & 127, k = e >> 14;   // W1[k][cin=i][cout=j]
    __nv_bfloat16 h, l; bf16_split(W1[e], h, l);
    int o = (k * CCH + j) * CCH + i;                    // [k][cout][cin]
    g_w1h[o] = h; g_w1l[o] = l;
}
__global__ void prep_wc(const float* __restrict__ W2) {
    int e = blockIdx.x * 256 + threadIdx.x;
    if (e >= 64 * CCH * CCH) return;
    int j = e & 127, i = (e >> 7) & 127, t = (e >> 14) & 7, c = e >> 17;
    int lo_[3], hi_[3];
    #pragma unroll
    for (int a = 0; a < 3; a++) {
        int cb = (c >> (2 - a)) & 1, tb = (t >> (2 - a)) & 1;
        if (cb == 0) { if (tb == 0) { lo_[a] = -1; hi_[a] = -1; } else { lo_[a] = 0; hi_[a] = 1; } }
        else         { if (tb == 0) { lo_[a] = -1; hi_[a] = 0;  } else { lo_[a] = 1; hi_[a] = 1; } }
    }
    float acc = 0.f;
    for (int o0 = lo_[0]; o0 <= hi_[0]; o0++)
        for (int o1 = lo_[1]; o1 <= hi_[1]; o1++)
            for (int o2 = lo_[2]; o2 <= hi_[2]; o2++) {
                int k = (o0 + 1) * 9 + (o1 + 1) * 3 + (o2 + 1);
                acc += W2[((size_t)k * CCH + i) * CCH + j];
            }
    __nv_bfloat16 h, l; bf16_split(acc, h, l);
    int o = (((c << 3) + t) * CCH + j) * CCH + i;       // [c][t][cout][cin]
    g_wch[o] = h; g_wcl[o] = l;
}

// ---------------- fused gather-GEMM: cp.async x3 stages + ldmatrix ------------
template <int IS_L2>
__global__ __launch_bounds__(256, 1) void conv_mma(
    const __nv_bfloat16* __restrict__ srcH, const __nv_bfloat16* __restrict__ srcL,
    const int* __restrict__ nbr,
    const __nv_bfloat16* __restrict__ wh, const __nv_bfloat16* __restrict__ wl,
    const float* __restrict__ bias,
    float* __restrict__ outF,
    __nv_bfloat16* __restrict__ outH, __nv_bfloat16* __restrict__ outL)
{
    extern __shared__ __align__(16) unsigned char smem_raw[];
    const uint32_t sb = smem_u32(smem_raw);

    const int tid  = threadIdx.x;
    const int wid  = tid >> 5, lane = tid & 31;
    const int g    = lane >> 2, t4 = lane & 3;
    const int m0   = blockIdx.x * BMT;
    const int child = IS_L2 ? (int)blockIdx.y : 0;
    const int niter = (IS_L2 ? 8 : 27) * 2;      // 2 K-chunks per tap

    // loader roles: 2 threads per row (A) / per cout row (B), 64B each
    const int ar = tid >> 1, seg = tid & 1;
    const int am = m0 + ar;

    // compute roles: warp tile 64(M) x 32(N); warps 2x4
    const int m0w = (wid >> 2) * 64;
    const int n0w = (wid & 3) * 32;

    // ldmatrix per-lane offsets
    const uint32_t a_lo = (uint32_t)((((lane >> 3) & 1) * 8 + (lane & 7)) * ASTRB + (lane >> 4) * 16);
    const uint32_t b_lo = (uint32_t)(((lane >= 16 ? 8 : 0) + (lane & 7)) * ASTRB + ((lane >> 3) & 1) * 16);

    float acc[4][4][4];
    #pragma unroll
    for (int mi = 0; mi < 4; mi++)
        #pragma unroll
        for (int ni = 0; ni < 4; ni++)
            #pragma unroll
            for (int r = 0; r < 4; r++) acc[mi][ni][r] = 0.f;

    auto issue = [&](int it) {
        const int tap = it >> 1, kc = (it & 1) * KCH;
        int tk; size_t woff;
        if (IS_L2) {
            int d0 = ((child >> 2) & 1) ? ((tap >> 2) & 1) : (((tap >> 2) & 1) - 1);
            int d1 = ((child >> 1) & 1) ? ((tap >> 1) & 1) : (((tap >> 1) & 1) - 1);
            int d2 = (child & 1)        ? (tap & 1)        : ((tap & 1) - 1);
            tk = (d0 + 1) * 9 + (d1 + 1) * 3 + (d2 + 1);
            woff = (size_t)((child << 3) + tap) * (CCH * CCH);
        } else { tk = tap; woff = (size_t)tap * (CCH * CCH); }

        const int idx = (am < NVOX) ? __ldg(nbr + am * 27 + tk) : NVOX;
        const char* aH = (const char*)(srcH + (size_t)idx * CCH + kc) + seg * 64;
        const char* aL = (const char*)(srcL + (size_t)idx * CCH + kc) + seg * 64;
        const char* bH = (const char*)(wh + woff + (size_t)ar * CCH + kc) + seg * 64;
        const char* bL = (const char*)(wl + woff + (size_t)ar * CCH + kc) + seg * 64;

        const uint32_t st = sb + (uint32_t)(it % NSTG) * STAGE;
        const uint32_t ad = st + ar * ASTRB + seg * 64;
        const uint32_t bd = st + 2 * TILE_B + ar * ASTRB + seg * 64;
        #pragma unroll
        for (int q = 0; q < 4; q++) {
            CP16(ad + q * 16,              aH + q * 16);
            CP16(ad + TILE_B + q * 16,     aL + q * 16);
            CP16(bd + q * 16,              bH + q * 16);
            CP16(bd + TILE_B + q * 16,     bL + q * 16);
        }
        CP_COMMIT();
    };

    // prologue: fill stages 0, 1
    issue(0);
    issue(1);

    for (int it = 0; it < niter; ++it) {
        if (it >= niter - 1) { CP_WAIT0(); } else { CP_WAIT1(); }
        __syncthreads();
        if (it + 2 < niter) issue(it + 2);

        const uint32_t st = sb + (uint32_t)(it % NSTG) * STAGE;
        const uint32_t Ah = st, Al = st + TILE_B, Bh = st + 2 * TILE_B, Bl = st + 3 * TILE_B;
        const uint32_t abase = (uint32_t)(m0w * ASTRB) + a_lo;
        const uint32_t bbase = (uint32_t)(n0w * ASTRB) + b_lo;

        #pragma unroll
        for (int ks = 0; ks < 4; ks++) {
            const uint32_t kb = ks * 32;
            uint32_t ah[4][4], al[4][4], bh[2][4], bl[2][4];
            #pragma unroll
            for (int mi = 0; mi < 4; mi++) {
                const uint32_t ra = abase + mi * (16 * ASTRB) + kb;
                ldsm4(ah[mi], Ah + ra);
                ldsm4(al[mi], Al + ra);
            }
            #pragma unroll
            for (int nj = 0; nj < 2; nj++) {
                const uint32_t rb = bbase + nj * (16 * ASTRB) + kb;
                ldsm4(bh[nj], Bh + rb);
                ldsm4(bl[nj], Bl + rb);
            }
            #pragma unroll
            for (int mi = 0; mi < 4; mi++)
                #pragma unroll
                for (int ni = 0; ni < 4; ni++)
                    mma_bf16(acc[mi][ni], ah[mi], &bh[ni >> 1][(ni & 1) * 2]);
            #pragma unroll
            for (int mi = 0; mi < 4; mi++)
                #pragma unroll
                for (int ni = 0; ni < 4; ni++)
                    mma_bf16(acc[mi][ni], ah[mi], &bl[ni >> 1][(ni & 1) * 2]);
            #pragma unroll
            for (int mi = 0; mi < 4; mi++)
                #pragma unroll
                for (int ni = 0; ni < 4; ni++)
                    mma_bf16(acc[mi][ni], al[mi], &bh[ni >> 1][(ni & 1) * 2]);
        }
    }

    // ---- epilogue: bias + SiLU + store ----
    #pragma unroll
    for (int mi = 0; mi < 4; mi++) {
        #pragma unroll
        for (int half = 0; half < 2; half++) {
            const int gm = m0 + m0w + mi * 16 + g + half * 8;
            if (gm >= NVOX) continue;
            #pragma unroll
            for (int ni = 0; ni < 4; ni++) {
                const int col = n0w + ni * 8 + t4 * 2;
                float x0 = acc[mi][ni][half * 2 + 0] + __ldg(bias + col);
                float x1 = acc[mi][ni][half * 2 + 1] + __ldg(bias + col + 1);
                float y0 = x0 / (1.f + __expf(-x0));
                float y1 = x1 / (1.f + __expf(-x1));
                if (IS_L2) {
                    float2* op = (float2*)(outF + ((size_t)8 * gm + child) * CCH + col);
                    *op = make_float2(y0, y1);
                } else {
                    __nv_bfloat16 h0, l0, h1, l1;
                    bf16_split(y0, h0, l0); bf16_split(y1, h1, l1);
                    *(uint32_t*)(outH + (size_t)gm * CCH + col) = pack2(h0, h1);
                    *(uint32_t*)(outL + (size_t)gm * CCH + col) = pack2(l0, l1);
                }
            }
        }
    }
}

// ---------------------------------------------------------------------------
extern "C" void kernel_launch(void* const* d_in, const int* in_sizes, int n_in,
                              void* d_out, int out_size) {
    const float* feats = (const float*)d_in[0];
    const float* W1    = (const float*)d_in[1];
    const float* b1    = (const float*)d_in[2];
    const float* W2    = (const float*)d_in[3];
    const float* b2    = (const float*)d_in[4];
    const int*   nbr1  = (const int*)d_in[5];
    float* out = (float*)d_out;
    (void)in_sizes; (void)n_in; (void)out_size;

    void *fh, *fl, *h1h, *h1l, *w1h, *w1l, *wch, *wcl;
    cudaGetSymbolAddress(&fh,  g_fh);
    cudaGetSymbolAddress(&fl,  g_fl);
    cudaGetSymbolAddress(&h1h, g_h1h);
    cudaGetSymbolAddress(&h1l, g_h1l);
    cudaGetSymbolAddress(&w1h, g_w1h);
    cudaGetSymbolAddress(&w1l, g_w1l);
    cudaGetSymbolAddress(&wch, g_wch);
    cudaGetSymbolAddress(&wcl, g_wcl);

    cudaFuncSetAttribute(conv_mma<0>, cudaFuncAttributeMaxDynamicSharedMemorySize, SMEM_BYTES);
    cudaFuncSetAttribute(conv_mma<1>, cudaFuncAttributeMaxDynamicSharedMemorySize, SMEM_BYTES);

    prep_feats<<<(NVOX * CCH + 255) / 256, 256>>>(feats);
    prep_w1<<<(K27 * CCH * CCH + 255) / 256, 256>>>(W1);
    prep_wc<<<(64 * CCH * CCH + 255) / 256, 256>>>(W2);

    // layer 1: feats(split) -> h1(split)
    conv_mma<0><<<dim3(GRIDM, 1), 256, SMEM_BYTES>>>(
        (const __nv_bfloat16*)fh, (const __nv_bfloat16*)fl, nbr1,
        (const __nv_bfloat16*)w1h, (const __nv_bfloat16*)w1l, b1,
        nullptr, (__nv_bfloat16*)h1h, (__nv_bfloat16*)h1l);

    // layer 2: h1(split) -> out
    conv_mma<1><<<dim3(GRIDM, 8), 256, SMEM_BYTES>>>(
        (const __nv_bfloat16*)h1h, (const __nv_bfloat16*)h1l, nbr1,
        (const __nv_bfloat16*)wch, (const __nv_bfloat16*)wcl, b2,
        out, nullptr, nullptr);
}